// round 16
// baseline (speedup 1.0000x reference)
#include <cuda_runtime.h>
#include <cstdint>

// FPS: B=2, Npb=131072, stride=32 -> M=4096 samples, 4095 serial rounds.
// 64 CTAs/batch * 256 thr * 8 pts/thr (128 CTAs: single wave, spin-safe).
// R16: counters removed entirely. Each CTA publishes ONE self-validating
// 32B packet (two 16B halves, each carrying w=(t<<17)|tail17 freshness +
// payload incl. winner coords) with plain volatile stores. warp0 of every
// CTA polls the 64 slots DIRECTLY (2 slots/lane, 4 independent 16B loads
// per iteration, spread over 16 L2 lines) until all halves are fresh --
// when the successful iteration returns, the payload is already in
// registers: detect and consume are one round trip. Batch argmax over the
// 64 packets via __reduce_max. Parity double-buffered; freshness words make
// stale/replayed data self-rejecting (no reset kernel needed).

#define NBATCH 2
#define CPB    64
#define TPB    256
#define PPT    8       // CPB*TPB*PPT = 131072
#define NPB    131072
#define MSAMP  4096
#define NW     (TPB / 32)
#define FLTMAX 3.402823466e38f

typedef unsigned long long u64;

struct __align__(32) Slot { uint4 a; uint4 b; };
// halfA = {dist_bits, w, x, y}   halfB = {z, w, 0, 0}
// w = (t << 17) | tail17,  tail17 = 0x1FFFF - in_batch_idx
__device__ Slot g_slot[2][NBATCH][CPB];        // [parity][batch][cta]

__device__ __forceinline__ u64 f2pack(float lo, float hi) {
    u64 r; asm("mov.b64 %0, {%1,%2};" : "=l"(r) : "f"(lo), "f"(hi)); return r;
}
__device__ __forceinline__ void f2unpack(float& lo, float& hi, u64 v) {
    asm("mov.b64 {%0,%1}, %2;" : "=f"(lo), "=f"(hi) : "l"(v));
}
__device__ __forceinline__ u64 addx2(u64 a, u64 b) {   // per-lane IEEE rn add
    u64 r; asm("add.rn.f32x2 %0, %1, %2;" : "=l"(r) : "l"(a), "l"(b)); return r;
}
__device__ __forceinline__ u64 mulx2(u64 a, u64 b) {   // per-lane IEEE rn mul
    u64 r; asm("mul.rn.f32x2 %0, %1, %2;" : "=l"(r) : "l"(a), "l"(b)); return r;
}
__device__ __forceinline__ uint4 ldv(const uint4* p) {
    uint4 v;
    asm volatile("ld.volatile.global.v4.u32 {%0,%1,%2,%3}, [%4];"
                 : "=r"(v.x), "=r"(v.y), "=r"(v.z), "=r"(v.w) : "l"(p));
    return v;
}
__device__ __forceinline__ void stv(uint4* p, uint4 v) {
    asm volatile("st.volatile.global.v4.u32 [%0], {%1,%2,%3,%4};"
                 :: "l"(p), "r"(v.x), "r"(v.y), "r"(v.z), "r"(v.w));
}

__global__ void __launch_bounds__(TPB, 1)
fps_kernel(const float4* __restrict__ pts, float* __restrict__ out)
{
    const int c    = blockIdx.x;          // CTA within batch (0..63)
    const int b    = blockIdx.y;          // batch
    const int tid  = threadIdx.x;
    const int lane = tid & 31;
    const int wid  = tid >> 5;

    const int lbase = c * (TPB * PPT);    // in-batch base index of this CTA
    const int gbase = b * NPB + lbase;
    const float4* __restrict__ bpts = pts + (size_t)b * NPB;

    // Register-resident point state; coords packed 2-per-u64 for f32x2 math.
    u64 x2[PPT / 2], y2[PPT / 2], z2[PPT / 2];
    float dist[PPT];
    unsigned tail[PPT];                   // 0x1FFFF - in_batch_idx (17 bits)
#pragma unroll
    for (int i = 0; i < PPT / 2; ++i) {
        float4 v0 = pts[gbase + (2 * i) * TPB + tid];
        float4 v1 = pts[gbase + (2 * i + 1) * TPB + tid];
        x2[i] = f2pack(v0.y, v1.y);
        y2[i] = f2pack(v0.z, v1.z);
        z2[i] = f2pack(v0.w, v1.w);
        dist[2 * i] = FLTMAX; dist[2 * i + 1] = FLTMAX;
        tail[2 * i]     = 0x1FFFFu - (unsigned)(lbase + (2 * i) * TPB + tid);
        tail[2 * i + 1] = 0x1FFFFu - (unsigned)(lbase + (2 * i + 1) * TPB + tid);
    }

    // Seed sample = point 0 of the batch (pointops convention)
    float4 p0 = bpts[0];
    float sx = p0.y, sy = p0.z, sz = p0.w;
    if (c == 0 && tid == 0)
        ((float4*)out)[(size_t)b * MSAMP] = p0;

    __shared__ unsigned s_db[NW], s_tl[NW];
    __shared__ float    s_x[NW], s_y[NW], s_z[NW];
    __shared__ float    s_new[3];

    for (int t = 1; t < MSAMP; ++t) {
        const unsigned tgt = (unsigned)t;
        // negate once (exact); x + (-s) is bit-identical to x - s in rn
        u64 nsx = f2pack(-sx, -sx);
        u64 nsy = f2pack(-sy, -sy);
        u64 nsz = f2pack(-sz, -sz);

        // ---- local dist update + per-thread argmax (bit compare == float
        // compare for non-negative f32; strict > keeps lowest idx since idx
        // ascends within the thread -> matches jnp.argmax first-max) ----
        unsigned bdb = 0u, btl = 0u;
        float bx = 0.f, by = 0.f, bz = 0.f;
#pragma unroll
        for (int i = 0; i < PPT / 2; ++i) {
            u64 dx = addx2(x2[i], nsx);
            u64 dy = addx2(y2[i], nsy);
            u64 dz = addx2(z2[i], nsz);
            // unfused, left-to-right (dx*dx + dy*dy) + dz*dz == reference
            u64 s = addx2(addx2(mulx2(dx, dx), mulx2(dy, dy)), mulx2(dz, dz));
            float d0, d1; f2unpack(d0, d1, s);
            float nd0 = fminf(dist[2 * i], d0);
            float nd1 = fminf(dist[2 * i + 1], d1);
            dist[2 * i] = nd0; dist[2 * i + 1] = nd1;
            unsigned db0 = __float_as_uint(nd0);
            unsigned db1 = __float_as_uint(nd1);
            float px0, px1, py0, py1, pz0, pz1;
            f2unpack(px0, px1, x2[i]);
            f2unpack(py0, py1, y2[i]);
            f2unpack(pz0, pz1, z2[i]);
            if (db0 > bdb) { bdb = db0; btl = tail[2 * i];
                             bx = px0; by = py0; bz = pz0; }
            if (db1 > bdb) { bdb = db1; btl = tail[2 * i + 1];
                             bx = px1; by = py1; bz = pz1; }
        }

        // ---- warp argmax: max dist-bits, tie -> max tail (= lowest idx) ----
        unsigned m  = __reduce_max_sync(0xFFFFFFFFu, bdb);
        unsigned mt = __reduce_max_sync(0xFFFFFFFFu, (bdb == m) ? btl : 0u);
        if (bdb == m && btl == mt) {      // unique winning lane
            s_db[wid] = m; s_tl[wid] = mt;
            s_x[wid] = bx; s_y[wid] = by; s_z[wid] = bz;
        }
        __syncthreads();

        if (wid == 0) {
            // ---- block argmax over NW warp winners ----
            unsigned db2 = (lane < NW) ? s_db[lane] : 0u;
            unsigned tl2 = (lane < NW) ? s_tl[lane] : 0u;
            unsigned m2  = __reduce_max_sync(0xFFFFFFFFu, db2);
            unsigned mt2 = __reduce_max_sync(0xFFFFFFFFu, (db2 == m2) ? tl2 : 0u);

            // ---- publish: winning lane stores the self-validating packet
            // (plain volatile stores; freshness word replaces all ordering) --
            if (db2 == m2 && tl2 == mt2) {
                unsigned w = (tgt << 17) | mt2;
                Slot* sp = &g_slot[t & 1][b][c];
                stv(&sp->b, make_uint4(__float_as_uint(s_z[lane]), w, 0u, 0u));
                stv(&sp->a, make_uint4(m2, w, __float_as_uint(s_x[lane]),
                                       __float_as_uint(s_y[lane])));
            }

            // ---- detect == consume: poll the 64 slots directly (2/lane,
            // 4 independent 16B loads spread over 16 L2 lines). When the
            // successful iteration returns, payload is already in registers.
            // Overwrite-safety: slot@t+2 (same parity) is written only after
            // its CTA consumed t+1, which requires every CTA published t+1,
            // which requires every CTA consumed t -> no poller still needs
            // (or can observe a torn) round-t slot. Stale replay data has
            // w>>17 != t and is simply waited out. ----
            Slot* s0 = &g_slot[t & 1][b][lane];
            Slot* s1 = &g_slot[t & 1][b][lane + 32];
            uint4 A0, B0, A1, B1;
            do {
                A0 = ldv(&s0->a); B0 = ldv(&s0->b);
                A1 = ldv(&s1->a); B1 = ldv(&s1->b);
            } while ((A0.y >> 17) != tgt || (B0.y >> 17) != tgt ||
                     (A1.y >> 17) != tgt || (B1.y >> 17) != tgt);

            // fold the lane's two candidates (same t prefix: compare w raw)
            unsigned db3 = A0.x, w3 = A0.y;
            float fx = __uint_as_float(A0.z), fy = __uint_as_float(A0.w);
            float fz = __uint_as_float(B0.x);
            if (A1.x > db3 || (A1.x == db3 && A1.y > w3)) {
                db3 = A1.x; w3 = A1.y;
                fx = __uint_as_float(A1.z); fy = __uint_as_float(A1.w);
                fz = __uint_as_float(B1.x);
            }

            // ---- batch argmax over the folded candidates ----
            unsigned m3 = __reduce_max_sync(0xFFFFFFFFu, db3);
            unsigned mw = __reduce_max_sync(0xFFFFFFFFu, (db3 == m3) ? w3 : 0u);
            int win = (db3 == m3 && w3 == mw);
            unsigned wl = 31 - __clz(__ballot_sync(0xFFFFFFFFu, win));
            float wx = __shfl_sync(0xFFFFFFFFu, fx, wl);
            float wy = __shfl_sync(0xFFFFFFFFu, fy, wl);
            float wz = __shfl_sync(0xFFFFFFFFu, fz, wl);

            if (lane == 0) {
                s_new[0] = wx; s_new[1] = wy; s_new[2] = wz;
                if (c == 0) {
                    float* o = out + ((size_t)b * MSAMP + t) * 4;
                    o[0] = (float)b; o[1] = wx; o[2] = wy; o[3] = wz;
                }
            }
        }
        __syncthreads();
        sx = s_new[0]; sy = s_new[1]; sz = s_new[2];
    }
}

extern "C" void kernel_launch(void* const* d_in, const int* in_sizes, int n_in,
                              void* d_out, int out_size) {
    (void)in_sizes; (void)n_in; (void)out_size;
    const float4* pts = (const float4*)d_in[0];
    // Geometry fixed by the problem instance: N=262144, B=2, stride=32.
    dim3 grid(CPB, NBATCH);
    fps_kernel<<<grid, TPB>>>(pts, (float*)d_out);
}

// round 17
// speedup vs baseline: 2.2447x; 2.2447x over previous
#include <cuda_runtime.h>
#include <cstdint>

// FPS: B=2, Npb=131072, stride=32 -> M=4096 samples, 4095 serial rounds.
// 64 CTAs/batch * 256 thr * 8 pts/thr (128 CTAs: single wave, spin-safe).
// R17 = R15 + software-pipelined ring poll. Publish: each CTA stores ONE
// self-validating 32B packet (two 16B halves, each carrying
// w=(t<<17)|tail17 freshness + payload incl. winner coords) with plain
// volatile stores, plus one relaxed red.add to a counter (two 256B-spaced
// lines, 32 adds each). Detect: warp0 polls the two 4B counters with FOUR
// load-pairs in flight, issuing a new pair every ~75 cyc (dependent-IADD
// delay chains); checks examine the oldest sample -> counters are sampled
// ~every 75 cyc instead of once per L2 round trip, shrinking the
// max-of-64-CTAs detection-quantization term (~270 -> ~75 cyc). Counters
// are monotonic within a replay so any satisfying sample is valid. Consume:
// slots read ONCE, validated by freshness word. Parity double-buffered.

#define NBATCH 2
#define CPB    64
#define TPB    256
#define PPT    8       // CPB*TPB*PPT = 131072
#define NPB    131072
#define MSAMP  4096
#define NW     (TPB / 32)
#define FLTMAX 3.402823466e38f

typedef unsigned long long u64;

struct __align__(32) Slot { uint4 a; uint4 b; };
// halfA = {dist_bits, w, x, y}   halfB = {z, w, 0, 0}
// w = (t << 17) | tail17,  tail17 = 0x1FFFF - in_batch_idx
__device__ Slot g_slot[2][NBATCH][CPB];        // [parity][batch][cta]

struct __align__(256) Cnt { unsigned v; unsigned _pad[63]; };
__device__ Cnt g_cnt[2][NBATCH][2];            // [parity][batch][half]

__global__ void reset_kernel() {
    int i = threadIdx.x;
    if (i < 2 * NBATCH * 2)
        g_cnt[i >> 2][(i >> 1) & 1][i & 1].v = 0u;
}

__device__ __forceinline__ u64 f2pack(float lo, float hi) {
    u64 r; asm("mov.b64 %0, {%1,%2};" : "=l"(r) : "f"(lo), "f"(hi)); return r;
}
__device__ __forceinline__ void f2unpack(float& lo, float& hi, u64 v) {
    asm("mov.b64 {%0,%1}, %2;" : "=f"(lo), "=f"(hi) : "l"(v));
}
__device__ __forceinline__ u64 addx2(u64 a, u64 b) {   // per-lane IEEE rn add
    u64 r; asm("add.rn.f32x2 %0, %1, %2;" : "=l"(r) : "l"(a), "l"(b)); return r;
}
__device__ __forceinline__ u64 mulx2(u64 a, u64 b) {   // per-lane IEEE rn mul
    u64 r; asm("mul.rn.f32x2 %0, %1, %2;" : "=l"(r) : "l"(a), "l"(b)); return r;
}
__device__ __forceinline__ uint4 ldv(const uint4* p) {
    uint4 v;
    asm volatile("ld.volatile.global.v4.u32 {%0,%1,%2,%3}, [%4];"
                 : "=r"(v.x), "=r"(v.y), "=r"(v.z), "=r"(v.w) : "l"(p));
    return v;
}
__device__ __forceinline__ void stv(uint4* p, uint4 v) {
    asm volatile("st.volatile.global.v4.u32 [%0], {%1,%2,%3,%4};"
                 :: "l"(p), "r"(v.x), "r"(v.y), "r"(v.z), "r"(v.w));
}
__device__ __forceinline__ void red_add_rlx(unsigned* p, unsigned v) {
    asm volatile("red.relaxed.gpu.global.add.u32 [%0], %1;" :: "l"(p), "r"(v));
}
__device__ __forceinline__ unsigned ld_rlx_u32(const unsigned* p) {
    unsigned v;
    asm volatile("ld.relaxed.gpu.global.u32 %0, [%1];" : "=r"(v) : "l"(p));
    return v;
}
// ~64-cycle dependent-ALU delay; asm volatile keeps issue order vs the
// volatile counter loads (both are volatile asm -> not reordered).
__device__ __forceinline__ void delay64(unsigned& j) {
#pragma unroll
    for (int k = 0; k < 16; ++k)
        asm volatile("add.s32 %0, %0, 1;" : "+r"(j));
}

__global__ void __launch_bounds__(TPB, 1)
fps_kernel(const float4* __restrict__ pts, float* __restrict__ out)
{
    const int c    = blockIdx.x;          // CTA within batch (0..63)
    const int b    = blockIdx.y;          // batch
    const int tid  = threadIdx.x;
    const int lane = tid & 31;
    const int wid  = tid >> 5;

    const int lbase = c * (TPB * PPT);    // in-batch base index of this CTA
    const int gbase = b * NPB + lbase;
    const float4* __restrict__ bpts = pts + (size_t)b * NPB;

    // Register-resident point state; coords packed 2-per-u64 for f32x2 math.
    u64 x2[PPT / 2], y2[PPT / 2], z2[PPT / 2];
    float dist[PPT];
    unsigned tail[PPT];                   // 0x1FFFF - in_batch_idx (17 bits)
#pragma unroll
    for (int i = 0; i < PPT / 2; ++i) {
        float4 v0 = pts[gbase + (2 * i) * TPB + tid];
        float4 v1 = pts[gbase + (2 * i + 1) * TPB + tid];
        x2[i] = f2pack(v0.y, v1.y);
        y2[i] = f2pack(v0.z, v1.z);
        z2[i] = f2pack(v0.w, v1.w);
        dist[2 * i] = FLTMAX; dist[2 * i + 1] = FLTMAX;
        tail[2 * i]     = 0x1FFFFu - (unsigned)(lbase + (2 * i) * TPB + tid);
        tail[2 * i + 1] = 0x1FFFFu - (unsigned)(lbase + (2 * i + 1) * TPB + tid);
    }

    // Seed sample = point 0 of the batch (pointops convention)
    float4 p0 = bpts[0];
    float sx = p0.y, sy = p0.z, sz = p0.w;
    if (c == 0 && tid == 0)
        ((float4*)out)[(size_t)b * MSAMP] = p0;

    __shared__ unsigned s_db[NW], s_tl[NW];
    __shared__ float    s_x[NW], s_y[NW], s_z[NW];
    __shared__ float    s_new[3];

    unsigned junk = (unsigned)tid;        // delay-chain carrier

    for (int t = 1; t < MSAMP; ++t) {
        const unsigned tgt = (unsigned)t;
        // negate once (exact); x + (-s) is bit-identical to x - s in rn
        u64 nsx = f2pack(-sx, -sx);
        u64 nsy = f2pack(-sy, -sy);
        u64 nsz = f2pack(-sz, -sz);

        // ---- local dist update + per-thread argmax (bit compare == float
        // compare for non-negative f32; strict > keeps lowest idx since idx
        // ascends within the thread -> matches jnp.argmax first-max) ----
        unsigned bdb = 0u, btl = 0u;
        float bx = 0.f, by = 0.f, bz = 0.f;
#pragma unroll
        for (int i = 0; i < PPT / 2; ++i) {
            u64 dx = addx2(x2[i], nsx);
            u64 dy = addx2(y2[i], nsy);
            u64 dz = addx2(z2[i], nsz);
            // unfused, left-to-right (dx*dx + dy*dy) + dz*dz == reference
            u64 s = addx2(addx2(mulx2(dx, dx), mulx2(dy, dy)), mulx2(dz, dz));
            float d0, d1; f2unpack(d0, d1, s);
            float nd0 = fminf(dist[2 * i], d0);
            float nd1 = fminf(dist[2 * i + 1], d1);
            dist[2 * i] = nd0; dist[2 * i + 1] = nd1;
            unsigned db0 = __float_as_uint(nd0);
            unsigned db1 = __float_as_uint(nd1);
            float px0, px1, py0, py1, pz0, pz1;
            f2unpack(px0, px1, x2[i]);
            f2unpack(py0, py1, y2[i]);
            f2unpack(pz0, pz1, z2[i]);
            if (db0 > bdb) { bdb = db0; btl = tail[2 * i];
                             bx = px0; by = py0; bz = pz0; }
            if (db1 > bdb) { bdb = db1; btl = tail[2 * i + 1];
                             bx = px1; by = py1; bz = pz1; }
        }

        // ---- warp argmax: max dist-bits, tie -> max tail (= lowest idx) ----
        unsigned m  = __reduce_max_sync(0xFFFFFFFFu, bdb);
        unsigned mt = __reduce_max_sync(0xFFFFFFFFu, (bdb == m) ? btl : 0u);
        if (bdb == m && btl == mt) {      // unique winning lane
            s_db[wid] = m; s_tl[wid] = mt;
            s_x[wid] = bx; s_y[wid] = by; s_z[wid] = bz;
        }
        __syncthreads();

        if (wid == 0) {
            // ---- block argmax over NW warp winners ----
            unsigned db2 = (lane < NW) ? s_db[lane] : 0u;
            unsigned tl2 = (lane < NW) ? s_tl[lane] : 0u;
            unsigned m2  = __reduce_max_sync(0xFFFFFFFFu, db2);
            unsigned mt2 = __reduce_max_sync(0xFFFFFFFFu, (db2 == m2) ? tl2 : 0u);

            // ---- publish: winning lane stores the self-validating packet
            // (plain volatile stores, NO RMW), then bumps its counter half
            // (relaxed add; freshness validation replaces release order) ----
            if (db2 == m2 && tl2 == mt2) {
                unsigned w = (tgt << 17) | mt2;
                Slot* sp = &g_slot[t & 1][b][c];
                stv(&sp->b, make_uint4(__float_as_uint(s_z[lane]), w, 0u, 0u));
                stv(&sp->a, make_uint4(m2, w, __float_as_uint(s_x[lane]),
                                       __float_as_uint(s_y[lane])));
                red_add_rlx(&g_cnt[t & 1][b][c >> 5].v, 1u);
            }

            // ---- detect: ring poll, 4 load-pairs in flight, new pair every
            // ~75 cyc -> counters sampled ~4x per L2 round trip, shrinking
            // the max-of-64-CTAs quantization term. Monotonic counters =>
            // any sample >= target is valid. '>=' safe: parity passes target
            // only after all CTAs consumed round t. ----
            const unsigned tg32 = 32u * (unsigned)((t + 1) >> 1);
            const unsigned* C0 = &g_cnt[t & 1][b][0].v;
            const unsigned* C1 = &g_cnt[t & 1][b][1].v;
            unsigned q0[4], q1[4];
#pragma unroll
            for (int i = 0; i < 4; ++i) {
                q0[i] = ld_rlx_u32(C0); q1[i] = ld_rlx_u32(C1);
                delay64(junk);
            }
            bool done = false;
            while (!done) {
#pragma unroll
                for (int r = 0; r < 4; ++r) {
                    if (q0[r] >= tg32 && q1[r] >= tg32) { done = true; break; }
                    q0[r] = ld_rlx_u32(C0); q1[r] = ld_rlx_u32(C1);
                    delay64(junk);
                }
            }

            // ---- consume: read 64 slots (2/lane), validate freshness;
            // re-read only if a relaxed add outran its packet (rare) ----
            Slot* s0 = &g_slot[t & 1][b][lane];
            Slot* s1 = &g_slot[t & 1][b][lane + 32];
            uint4 A0, B0, A1, B1;
            do {
                A0 = ldv(&s0->a); B0 = ldv(&s0->b);
                A1 = ldv(&s1->a); B1 = ldv(&s1->b);
            } while ((A0.y >> 17) != tgt || (B0.y >> 17) != tgt ||
                     (A1.y >> 17) != tgt || (B1.y >> 17) != tgt);

            // fold the lane's two candidates (same t prefix: compare w raw)
            unsigned db3 = A0.x, w3 = A0.y;
            float fx = __uint_as_float(A0.z), fy = __uint_as_float(A0.w);
            float fz = __uint_as_float(B0.x);
            if (A1.x > db3 || (A1.x == db3 && A1.y > w3)) {
                db3 = A1.x; w3 = A1.y;
                fx = __uint_as_float(A1.z); fy = __uint_as_float(A1.w);
                fz = __uint_as_float(B1.x);
            }

            // ---- batch argmax over the folded candidates ----
            unsigned m3 = __reduce_max_sync(0xFFFFFFFFu, db3);
            unsigned mw = __reduce_max_sync(0xFFFFFFFFu, (db3 == m3) ? w3 : 0u);
            int win = (db3 == m3 && w3 == mw);
            unsigned wl = 31 - __clz(__ballot_sync(0xFFFFFFFFu, win));
            float wx = __shfl_sync(0xFFFFFFFFu, fx, wl);
            float wy = __shfl_sync(0xFFFFFFFFu, fy, wl);
            float wz = __shfl_sync(0xFFFFFFFFu, fz, wl);

            if (lane == 0) {
                s_new[0] = wx; s_new[1] = wy; s_new[2] = wz;
                if (c == 0) {
                    float* o = out + ((size_t)b * MSAMP + t) * 4;
                    o[0] = (float)b; o[1] = wx; o[2] = wy; o[3] = wz;
                }
            }
        }
        __syncthreads();
        sx = s_new[0]; sy = s_new[1]; sz = s_new[2];
    }
    // keep junk live so the delay chains are never eliminated
    if (junk == 0xFFFFFFFFu && tid == TPB) out[0] = 0.f;  // never true
}

extern "C" void kernel_launch(void* const* d_in, const int* in_sizes, int n_in,
                              void* d_out, int out_size) {
    (void)in_sizes; (void)n_in; (void)out_size;
    const float4* pts = (const float4*)d_in[0];
    reset_kernel<<<1, 32>>>();                    // clears counters each replay
    dim3 grid(CPB, NBATCH);
    fps_kernel<<<grid, TPB>>>(pts, (float*)d_out);
}